// round 11
// baseline (speedup 1.0000x reference)
#include <cuda_runtime.h>
#include <math.h>
#include <stdint.h>

#define IMG_W 1024
#define IMG_H 1024
#define IMG_B 8
#define IMG_HW (IMG_H * IMG_W)

#define TX 32
#define TY 16
#define NTHR 512
#define NPAIR 4
#define NBLOCKS_BACK ((IMG_W / TX) * (IMG_H / TY) * 2)

// ---------------------------------------------------------------------------
// Scratch (allocation-free rule: __device__ globals; zero-initialized)
// ---------------------------------------------------------------------------
__device__ float2 g_sup2[(size_t)NPAIR * IMG_HW];
__device__ unsigned int g_max_bits;   // reset by last back block each launch
__device__ unsigned int g_done;

__device__ __forceinline__ int refl(int i, int n) {
    if (i < 0) i = -i;
    if (i >= n) i = 2 * n - 2 - i;
    return i;
}

// fast sigmoid: MUFU ex2 + approx reciprocal (smooth output path only)
__device__ __forceinline__ float sigm(float x) {
    float e = __expf(-x);
    float d = 1.0f + e;
    float r; asm("rcp.approx.f32 %0, %1;" : "=f"(r) : "f"(d));
    return r;
}

// ---------------------------------------------------------------------------
// Packed f32x2 primitives
// ---------------------------------------------------------------------------
__device__ __forceinline__ uint64_t f2add(uint64_t a, uint64_t b) {
    uint64_t r; asm("add.rn.f32x2 %0, %1, %2;" : "=l"(r) : "l"(a), "l"(b)); return r;
}
__device__ __forceinline__ uint64_t f2mul(uint64_t a, uint64_t b) {
    uint64_t r; asm("mul.rn.f32x2 %0, %1, %2;" : "=l"(r) : "l"(a), "l"(b)); return r;
}
__device__ __forceinline__ uint64_t f2fma(uint64_t a, uint64_t b, uint64_t c) {
    uint64_t r; asm("fma.rn.f32x2 %0, %1, %2, %3;" : "=l"(r) : "l"(a), "l"(b), "l"(c)); return r;
}
__device__ __forceinline__ uint64_t f2neg(uint64_t a) { return a ^ 0x8000000080000000ull; }

__device__ __forceinline__ uint64_t pack2(float lo, float hi) {
    return ((uint64_t)__float_as_uint(hi) << 32) | (uint64_t)__float_as_uint(lo);
}
__device__ __forceinline__ float plo(uint64_t v) { return __uint_as_float((unsigned)v); }
__device__ __forceinline__ float phi(uint64_t v) { return __uint_as_float((unsigned)(v >> 32)); }

#define NEG1_PK 0xBF800000BF800000ull

__device__ __forceinline__ uint64_t f2sub(uint64_t a, uint64_t b) {
    return f2fma(b, NEG1_PK, a);
}

// full TwoSum accumulate (sign-mixed sums): (ah, al) += (p, e)
__device__ __forceinline__ void f2_acc(uint64_t& ah, uint64_t& al,
                                       uint64_t p, uint64_t e) {
    uint64_t s  = f2add(ah, p);
    uint64_t bp = f2fma(ah, NEG1_PK, s);
    uint64_t ap = f2fma(bp, NEG1_PK, s);
    uint64_t eb = f2fma(bp, NEG1_PK, p);
    uint64_t ea = f2fma(ap, NEG1_PK, ah);
    ah = s;
    al = f2add(al, f2add(f2add(ea, eb), e));
}

// Kahan accumulate (all-positive sums; shorter chain): (ah, al) += (p, e)
__device__ __forceinline__ void f2_kacc(uint64_t& ah, uint64_t& al,
                                        uint64_t p, uint64_t e) {
    uint64_t s   = f2add(ah, p);
    uint64_t err = f2fma(s, NEG1_PK, ah);  // ah - s
    err = f2add(err, p);                   // (ah - s) + p
    al  = f2add(al, f2add(err, e));
    ah  = s;
}

// Fast2Sum renorm
__device__ __forceinline__ void f2_renorm(uint64_t& h, uint64_t& l) {
    uint64_t hh = f2add(h, l);
    uint64_t t  = f2fma(h, NEG1_PK, hh);
    l = f2fma(t, NEG1_PK, l);
    h = hh;
}

// packed df-const × df, renormalized
__device__ __forceinline__ void df2_mul_const(uint64_t Th, uint64_t Tl,
                                              uint64_t ah, uint64_t al,
                                              uint64_t& mh, uint64_t& ml) {
    uint64_t p = f2mul(Th, ah);
    uint64_t e = f2fma(Th, ah, f2neg(p));
    e = f2fma(Th, al, e);
    e = f2fma(Tl, ah, e);
    mh = f2add(p, e);
    ml = f2sub(e, f2sub(mh, p));
}

__device__ __forceinline__ uint4 pk4(uint64_t h, uint64_t l) {
    uint4 r; r.x = (unsigned)h; r.y = (unsigned)(h >> 32);
    r.z = (unsigned)l; r.w = (unsigned)(l >> 32); return r;
}
__device__ __forceinline__ void upk4(uint4 v, uint64_t& h, uint64_t& l) {
    h = ((uint64_t)v.y << 32) | v.x;
    l = ((uint64_t)v.w << 32) | v.z;
}

__device__ __forceinline__ bool dfp_gt(float ah, float al, float bh, float bl) {
    return (ah > bh) || (ah == bh && al > bl);
}

// ---------------------------------------------------------------------------
// Shared-memory overlay (bytes):
//   img (24x40 u64, 7680)   @ 0       live S1-S2
//   row (24x36 uint4,13824) @ 7680    live S2-S3
//   sm  (20x36 uint4,11520) @ 21504   live S3-SC
//   d   (20x34 uint4,10880) @ 0       live SC-SD
//   s   (20x34 uint4,10880) @ 33024   live SC-SD
//   g2  (18x34 uint4, 9792) @ 21504   live SD-SE
//   bin (18x34 uchar2,1224) @ 43904   live SD-SE
// ---------------------------------------------------------------------------
#define OFF_IMG 0
#define OFF_ROW 7680
#define OFF_SM  21504
#define OFF_D   0
#define OFF_S   33024
#define OFF_G2  21504
#define OFF_BIN 43904
#define SBUF_SZ 45128

// ---------------------------------------------------------------------------
// Fused front: img -> sep gauss -> sobel -> NMS -> sup (+max)
// ---------------------------------------------------------------------------
__global__ __launch_bounds__(NTHR) void fused_front_kernel(const float* __restrict__ img) {
    __shared__ __align__(16) unsigned char sbuf[SBUF_SZ];
    __shared__ float smax[NTHR / 32];

    uint64_t (*s_img)[40] = (uint64_t(*)[40])(sbuf + OFF_IMG);
    uint4    (*s_row)[36] = (uint4(*)[36])(sbuf + OFF_ROW);
    uint4    (*s_sm )[36] = (uint4(*)[36])(sbuf + OFF_SM);
    uint4    (*s_d  )[34] = (uint4(*)[34])(sbuf + OFF_D);
    uint4    (*s_s  )[34] = (uint4(*)[34])(sbuf + OFF_S);
    uint4    (*s_g2 )[34] = (uint4(*)[34])(sbuf + OFF_G2);
    uchar2   (*s_bin)[34] = (uchar2(*)[34])(sbuf + OFF_BIN);

    const int x0 = blockIdx.x * TX;
    const int y0 = blockIdx.y * TY;
    const int p  = blockIdx.z;
    const float* p0 = img + (size_t)(2 * p)     * IMG_HW;
    const float* p1 = img + (size_t)(2 * p + 1) * IMG_HW;
    const int tid = threadIdx.x;

    const float w5[5] = {0.054488684549640294f, 0.24420134200323337f,
                         0.4026199468935272f,  0.24420134200323337f,
                         0.054488684549640294f};
    uint64_t W[5];
#pragma unroll
    for (int k = 0; k < 5; k++) W[k] = pack2(w5[k], w5[k]);

    // ---- S1: load image tile (reflect once) ----
#pragma unroll 2
    for (int i = tid; i < 24 * 40; i += NTHR) {
        const int yy = i / 40, xx = i - yy * 40;
        const int gx = refl(x0 - 4 + xx, IMG_W);
        const int gy = refl(y0 - 4 + yy, IMG_H);
        const int gi = gy * IMG_W + gx;
        s_img[yy][xx] = pack2(p0[gi], p1[gi]);
    }
    __syncthreads();

    // ---- S2: row gaussian (x); all-positive -> Kahan ----
#pragma unroll 2
    for (int i = tid; i < 24 * 36; i += NTHR) {
        const int ry = i / 36, rx = i - ry * 36;
        uint64_t a0 = s_img[ry][rx];
        uint64_t ah = f2mul(W[0], a0);
        uint64_t al = f2fma(W[0], a0, f2neg(ah));
#pragma unroll
        for (int k = 1; k < 5; k++) {
            uint64_t ak = s_img[ry][rx + k];
            uint64_t pp = f2mul(W[k], ak);
            uint64_t ee = f2fma(W[k], ak, f2neg(pp));
            f2_kacc(ah, al, pp, ee);
        }
        s_row[ry][rx] = pk4(ah, al);
    }
    __syncthreads();

    // ---- S3: column gaussian (y); all-positive -> Kahan ----
#pragma unroll 2
    for (int i = tid; i < 20 * 36; i += NTHR) {
        const int sy = i / 36, sx = i - sy * 36;
        uint64_t h0, l0;
        upk4(s_row[sy][sx], h0, l0);
        uint64_t ah = f2mul(W[0], h0);
        uint64_t al = f2fma(W[0], h0, f2neg(ah));
        al = f2fma(W[0], l0, al);
#pragma unroll
        for (int k = 1; k < 5; k++) {
            uint64_t hk, lk;
            upk4(s_row[sy + k][sx], hk, lk);
            uint64_t pp = f2mul(W[k], hk);
            uint64_t ee = f2fma(W[k], hk, f2neg(pp));
            ee = f2fma(W[k], lk, ee);
            f2_kacc(ah, al, pp, ee);
        }
        s_sm[sy][sx] = pk4(ah, al);
    }
    __syncthreads();

    // ---- SC: per-row sobel intermediates  d = v2 - v0 (TwoSum),
    //          s = v0 + 2v1 + v2 (positive -> Kahan) ----
#pragma unroll 2
    for (int i = tid; i < 20 * 34; i += NTHR) {
        const int ry = i / 34, jx = i - ry * 34;
        uint64_t v0h, v0l, v1h, v1l, v2h, v2l;
        upk4(s_sm[ry][jx + 0], v0h, v0l);
        upk4(s_sm[ry][jx + 1], v1h, v1l);
        upk4(s_sm[ry][jx + 2], v2h, v2l);

        uint64_t dh = v2h, dl = v2l;
        f2_acc(dh, dl, f2neg(v0h), f2neg(v0l));

        uint64_t sh = v0h, sl = v0l;
        f2_kacc(sh, sl, f2add(v1h, v1h), f2add(v1l, v1l));
        f2_kacc(sh, sl, v2h, v2l);

        s_d[ry][jx] = pk4(dh, dl);
        s_s[ry][jx] = pk4(sh, sl);
    }
    __syncthreads();

    // ---- SD: gx = d0+2d1+d2, gy = s0-s2, g2 = gx^2+gy^2, bins (interior) ----
    const uint64_t T1H = pack2(0.41421357f,  0.41421357f);
    const uint64_t T1L = pack2(-7.3716195e-9f, -7.3716195e-9f);
    const uint64_t T2H = pack2(2.4142137f,   2.4142137f);
    const uint64_t T2L = pack2(-1.3773958e-7f, -1.3773958e-7f);

#pragma unroll 2
    for (int i = tid; i < 18 * 34; i += NTHR) {
        const int jy = i / 34, jx = i - jy * 34;
        uint64_t d0h, d0l, d1h, d1l, d2h, d2l, s0h, s0l, s2h, s2l;
        upk4(s_d[jy + 0][jx], d0h, d0l);
        upk4(s_d[jy + 1][jx], d1h, d1l);
        upk4(s_d[jy + 2][jx], d2h, d2l);
        upk4(s_s[jy + 0][jx], s0h, s0l);
        upk4(s_s[jy + 2][jx], s2h, s2l);

        uint64_t gxh = d0h, gxl = d0l;
        f2_acc(gxh, gxl, f2add(d1h, d1h), f2add(d1l, d1l));
        f2_acc(gxh, gxl, d2h, d2l);
        f2_renorm(gxh, gxl);

        uint64_t gyh = s0h, gyl = s0l;
        f2_acc(gyh, gyl, f2neg(s2h), f2neg(s2l));
        f2_renorm(gyh, gyl);

        uint64_t pa = f2mul(gxh, gxh);
        uint64_t ea = f2fma(gxh, gxh, f2neg(pa));
        ea = f2fma(f2add(gxh, gxh), gxl, ea);
        uint64_t pb = f2mul(gyh, gyh);
        uint64_t eb = f2fma(gyh, gyh, f2neg(pb));
        eb = f2fma(f2add(gyh, gyh), gyl, eb);
        uint64_t g2h = pa, g2l = ea;
        f2_acc(g2h, g2l, pb, eb);
        f2_renorm(g2h, g2l);
        s_g2[jy][jx] = pk4(g2h, g2l);

        if (jy >= 1 && jy <= TY && jx >= 1 && jx <= TX) {
            uint64_t sgx = gxh & 0x8000000080000000ull;
            uint64_t axh = gxh ^ sgx, axl = gxl ^ sgx;
            uint64_t sgy = gyh & 0x8000000080000000ull;
            uint64_t ayh = gyh ^ sgy, ayl = gyl ^ sgy;

            uint64_t m1h, m1l, m2h, m2l;
            df2_mul_const(T1H, T1L, axh, axl, m1h, m1l);
            df2_mul_const(T2H, T2L, axh, axl, m2h, m2l);

            uchar2 bb;
#pragma unroll
            for (int c = 0; c < 2; c++) {
                float AYH, AYL, M1Hf, M1Lf, M2Hf, M2Lf, GXH, GXL, GYH, GYL;
                if (c == 0) {
                    AYH = plo(ayh); AYL = plo(ayl);
                    M1Hf = plo(m1h); M1Lf = plo(m1l);
                    M2Hf = plo(m2h); M2Lf = plo(m2l);
                    GXH = plo(gxh); GXL = plo(gxl);
                    GYH = plo(gyh); GYL = plo(gyl);
                } else {
                    AYH = phi(ayh); AYL = phi(ayl);
                    M1Hf = phi(m1h); M1Lf = phi(m1l);
                    M2Hf = phi(m2h); M2Lf = phi(m2l);
                    GXH = phi(gxh); GXL = phi(gxl);
                    GYH = phi(gyh); GYL = phi(gyl);
                }
                unsigned char bin;
                if (AYH < M1Hf || (AYH == M1Hf && AYL < M1Lf)) bin = 0;
                else if (!(AYH < M2Hf || (AYH == M2Hf && AYL < M2Lf))) bin = 2;
                else {
                    const bool px = (GXH > 0.0f) || (GXH == 0.0f && GXL > 0.0f);
                    const bool py = (GYH > 0.0f) || (GYH == 0.0f && GYL > 0.0f);
                    bin = (px == py) ? 1 : 3;
                }
                if (c == 0) bb.x = bin; else bb.y = bin;
            }
            s_bin[jy][jx] = bb;
        }
    }
    __syncthreads();

    // ---- SE: NMS + sup + block max ----
    const int tx = tid & (TX - 1);
    const int ty = tid >> 5;

    uint64_t c_h, c_l;
    upk4(s_g2[ty + 1][tx + 1], c_h, c_l);
    const uchar2 bin2 = s_bin[ty + 1][tx + 1];

    float sup[2];
#pragma unroll
    for (int comp = 0; comp < 2; comp++) {
        const int bin = comp ? bin2.y : bin2.x;
        int ay, ax_, by, bx_;
        if (bin == 0)      { ay = ty + 1; ax_ = tx + 2; by = ty + 1; bx_ = tx + 0; }
        else if (bin == 2) { ay = ty + 0; ax_ = tx + 1; by = ty + 2; bx_ = tx + 1; }
        else if (bin == 1) { ay = ty + 2; ax_ = tx + 0; by = ty + 0; bx_ = tx + 2; }
        else               { ay = ty + 2; ax_ = tx + 2; by = ty + 0; bx_ = tx + 0; }

        uint64_t nAh, nAl, nBh, nBl;
        upk4(s_g2[ay][ax_], nAh, nAl);
        upk4(s_g2[by][bx_], nBh, nBl);

        float ch, cl, nah, nal, nbh, nbl;
        if (comp == 0) {
            ch = plo(c_h); cl = plo(c_l);
            nah = plo(nAh); nal = plo(nAl);
            nbh = plo(nBh); nbl = plo(nBl);
        } else {
            ch = phi(c_h); cl = phi(c_l);
            nah = phi(nAh); nal = phi(nAl);
            nbh = phi(nBh); nbl = phi(nBl);
        }

        float sv = 0.0f;
        if (dfp_gt(ch, cl, nah, nal) && dfp_gt(ch, cl, nbh, nbl))
            sv = sqrtf(ch);
        sup[comp] = sv;
    }

    g_sup2[(size_t)p * IMG_HW + (size_t)(y0 + ty) * IMG_W + (x0 + tx)] =
        make_float2(sup[0], sup[1]);

    float vmax = fmaxf(sup[0], sup[1]);
#pragma unroll
    for (int off = 16; off > 0; off >>= 1)
        vmax = fmaxf(vmax, __shfl_xor_sync(0xFFFFFFFF, vmax, off));
    const int wid = tid >> 5;
    if ((tid & 31) == 0) smax[wid] = vmax;
    __syncthreads();
    if (tid == 0) {
        float bmax = smax[0];
#pragma unroll
        for (int i = 1; i < NTHR / 32; i++) bmax = fmaxf(bmax, smax[i]);
        atomicMax(&g_max_bits, __float_as_uint(bmax));
    }
}

// ---------------------------------------------------------------------------
// Fused back: 4 batches (2 sup planes) per block; resets g_max at the end
// ---------------------------------------------------------------------------
__global__ __launch_bounds__(NTHR) void fused_back_kernel(float* __restrict__ out) {
    __shared__ float2   s_sup[2][18][34];
    __shared__ uint64_t s_str[2][18][34];

    const int x0 = blockIdx.x * TX;
    const int y0 = blockIdx.y * TY;
    const int q  = blockIdx.z;               // quad index: batches 4q..4q+3
    const int tid = threadIdx.x;
    const float2* sup0 = g_sup2 + (size_t)(2 * q)     * IMG_HW;
    const float2* sup1 = g_sup2 + (size_t)(2 * q + 1) * IMG_HW;

    // min(sup) == 0 exactly (NMS always suppresses some pixels)
    const float mx   = __uint_as_float(g_max_bits);
    const float high = mx * 0.25f;
    const float low  = mx * 0.1f;

#pragma unroll 2
    for (int i = tid; i < 18 * 34; i += NTHR) {
        const int yy = i / 34, xx = i - yy * 34;
        const int gx = refl(x0 - 1 + xx, IMG_W);
        const int gy = refl(y0 - 1 + yy, IMG_H);
        const int gi = gy * IMG_W + gx;
        const float2 a = sup0[gi];
        const float2 b = sup1[gi];
        s_sup[0][yy][xx] = a;
        s_sup[1][yy][xx] = b;
        s_str[0][yy][xx] = pack2(sigm(100.0f * (a.x - high)),
                                 sigm(100.0f * (a.y - high)));
        s_str[1][yy][xx] = pack2(sigm(100.0f * (b.x - high)),
                                 sigm(100.0f * (b.y - high)));
    }
    __syncthreads();   // also guarantees every thread consumed g_max_bits

    const int tx = tid & (TX - 1);
    const int ty = tid >> 5;
    const size_t idx = (size_t)(y0 + ty) * IMG_W + (x0 + tx);

#pragma unroll
    for (int j = 0; j < 2; j++) {
        uint64_t hs = s_str[j][ty + 0][tx + 0];
        hs = f2add(hs, s_str[j][ty + 0][tx + 1]);
        hs = f2add(hs, s_str[j][ty + 0][tx + 2]);
        hs = f2add(hs, s_str[j][ty + 1][tx + 0]);
        hs = f2add(hs, s_str[j][ty + 1][tx + 1]);
        hs = f2add(hs, s_str[j][ty + 1][tx + 2]);
        hs = f2add(hs, s_str[j][ty + 2][tx + 0]);
        hs = f2add(hs, s_str[j][ty + 2][tx + 1]);
        hs = f2add(hs, s_str[j][ty + 2][tx + 2]);

        const uint64_t sc = s_str[j][ty + 1][tx + 1];
        const float2  sv  = s_sup[j][ty + 1][tx + 1];

        const float s0 = plo(sc), s1 = phi(sc);
        const float w0 = sigm(100.0f * (sv.x - low)) * (1.0f - s0);
        const float w1 = sigm(100.0f * (sv.y - low)) * (1.0f - s1);
        const float m0 = s0 + w0 * sigm(100.0f * (plo(hs) - 0.5f));
        const float m1 = s1 + w1 * sigm(100.0f * (phi(hs) - 0.5f));

        out[(size_t)(4 * q + 2 * j)     * IMG_HW + idx] = m0;
        out[(size_t)(4 * q + 2 * j + 1) * IMG_HW + idx] = m1;
    }

    // last-finishing block resets scalars for the next graph replay
    if (tid == 0) {
        const unsigned t = atomicAdd(&g_done, 1u);
        if (t == (unsigned)(NBLOCKS_BACK - 1)) {
            g_max_bits = 0u;
            g_done = 0u;
        }
    }
}

// ---------------------------------------------------------------------------
extern "C" void kernel_launch(void* const* d_in, const int* in_sizes, int n_in,
                              void* d_out, int out_size) {
    const float* image = (const float*)d_in[0];
    float* out = (float*)d_out;

    dim3 grdF(IMG_W / TX, IMG_H / TY, NPAIR);
    fused_front_kernel<<<grdF, NTHR>>>(image);

    dim3 grdB(IMG_W / TX, IMG_H / TY, 2);
    fused_back_kernel<<<grdB, NTHR>>>(out);
}

// round 12
// speedup vs baseline: 1.1390x; 1.1390x over previous
#include <cuda_runtime.h>
#include <math.h>
#include <stdint.h>

#define IMG_W 1024
#define IMG_H 1024
#define IMG_B 8
#define IMG_HW (IMG_H * IMG_W)

#define TX 32
#define TY 16
#define NTHR 512
#define NPAIR 4
#define NBLOCKS_BACK ((IMG_W / TX) * (IMG_H / TY) * 2)

// ---------------------------------------------------------------------------
// Scratch (allocation-free rule: __device__ globals; zero-initialized)
// ---------------------------------------------------------------------------
__device__ float2 g_sup2[(size_t)NPAIR * IMG_HW];
__device__ unsigned int g_max_bits;   // reset by last back block each launch
__device__ unsigned int g_done;

__device__ __forceinline__ int refl(int i, int n) {
    if (i < 0) i = -i;
    if (i >= n) i = 2 * n - 2 - i;
    return i;
}

// fast sigmoid: MUFU ex2 + approx reciprocal (smooth output path only)
__device__ __forceinline__ float sigm(float x) {
    float e = __expf(-x);
    float d = 1.0f + e;
    float r; asm("rcp.approx.f32 %0, %1;" : "=f"(r) : "f"(d));
    return r;
}

// ---------------------------------------------------------------------------
// Packed f32x2 primitives
// ---------------------------------------------------------------------------
__device__ __forceinline__ uint64_t f2add(uint64_t a, uint64_t b) {
    uint64_t r; asm("add.rn.f32x2 %0, %1, %2;" : "=l"(r) : "l"(a), "l"(b)); return r;
}
__device__ __forceinline__ uint64_t f2mul(uint64_t a, uint64_t b) {
    uint64_t r; asm("mul.rn.f32x2 %0, %1, %2;" : "=l"(r) : "l"(a), "l"(b)); return r;
}
__device__ __forceinline__ uint64_t f2fma(uint64_t a, uint64_t b, uint64_t c) {
    uint64_t r; asm("fma.rn.f32x2 %0, %1, %2, %3;" : "=l"(r) : "l"(a), "l"(b), "l"(c)); return r;
}
__device__ __forceinline__ uint64_t f2neg(uint64_t a) { return a ^ 0x8000000080000000ull; }

__device__ __forceinline__ uint64_t pack2(float lo, float hi) {
    return ((uint64_t)__float_as_uint(hi) << 32) | (uint64_t)__float_as_uint(lo);
}
__device__ __forceinline__ float plo(uint64_t v) { return __uint_as_float((unsigned)v); }
__device__ __forceinline__ float phi(uint64_t v) { return __uint_as_float((unsigned)(v >> 32)); }

#define NEG1_PK 0xBF800000BF800000ull

__device__ __forceinline__ uint64_t f2sub(uint64_t a, uint64_t b) {
    return f2fma(b, NEG1_PK, a);
}

// full TwoSum accumulate (sign-mixed sums): (ah, al) += (p, e)
__device__ __forceinline__ void f2_acc(uint64_t& ah, uint64_t& al,
                                       uint64_t p, uint64_t e) {
    uint64_t s  = f2add(ah, p);
    uint64_t bp = f2fma(ah, NEG1_PK, s);
    uint64_t ap = f2fma(bp, NEG1_PK, s);
    uint64_t eb = f2fma(bp, NEG1_PK, p);
    uint64_t ea = f2fma(ap, NEG1_PK, ah);
    ah = s;
    al = f2add(al, f2add(f2add(ea, eb), e));
}

// Kahan accumulate (all-positive sums; shorter chain): (ah, al) += (p, e)
__device__ __forceinline__ void f2_kacc(uint64_t& ah, uint64_t& al,
                                        uint64_t p, uint64_t e) {
    uint64_t s   = f2add(ah, p);
    uint64_t err = f2fma(s, NEG1_PK, ah);  // ah - s
    err = f2add(err, p);                   // (ah - s) + p
    al  = f2add(al, f2add(err, e));
    ah  = s;
}

// Fast2Sum renorm
__device__ __forceinline__ void f2_renorm(uint64_t& h, uint64_t& l) {
    uint64_t hh = f2add(h, l);
    uint64_t t  = f2fma(h, NEG1_PK, hh);
    l = f2fma(t, NEG1_PK, l);
    h = hh;
}

// packed df-const × df, renormalized
__device__ __forceinline__ void df2_mul_const(uint64_t Th, uint64_t Tl,
                                              uint64_t ah, uint64_t al,
                                              uint64_t& mh, uint64_t& ml) {
    uint64_t p = f2mul(Th, ah);
    uint64_t e = f2fma(Th, ah, f2neg(p));
    e = f2fma(Th, al, e);
    e = f2fma(Tl, ah, e);
    mh = f2add(p, e);
    ml = f2sub(e, f2sub(mh, p));
}

__device__ __forceinline__ uint4 pk4(uint64_t h, uint64_t l) {
    uint4 r; r.x = (unsigned)h; r.y = (unsigned)(h >> 32);
    r.z = (unsigned)l; r.w = (unsigned)(l >> 32); return r;
}
__device__ __forceinline__ void upk4(uint4 v, uint64_t& h, uint64_t& l) {
    h = ((uint64_t)v.y << 32) | v.x;
    l = ((uint64_t)v.w << 32) | v.z;
}

__device__ __forceinline__ bool dfp_gt(float ah, float al, float bh, float bl) {
    return (ah > bh) || (ah == bh && al > bl);
}

// ---------------------------------------------------------------------------
// Shared-memory overlay (bytes):
//   img (24x40 u64, 7680)   @ 0       live S1-S2
//   row (24x36 uint4,13824) @ 7680    live S2-S3
//   sm  (20x36 uint4,11520) @ 21504   live S3-SC
//   d   (20x34 uint4,10880) @ 0       live SC-SD
//   s   (20x34 uint4,10880) @ 33024   live SC-SD
//   g2  (18x34 uint4, 9792) @ 21504   live SD-SE
//   bin (18x34 uchar2,1224) @ 43904   live SD-SE
// ---------------------------------------------------------------------------
#define OFF_IMG 0
#define OFF_ROW 7680
#define OFF_SM  21504
#define OFF_D   0
#define OFF_S   33024
#define OFF_G2  21504
#define OFF_BIN 43904
#define SBUF_SZ 45128

// ---------------------------------------------------------------------------
// Fused front: img -> sep gauss -> sobel -> NMS -> sup (+max)
// __launch_bounds__(512, 4): pin regs to 32 -> 4 blocks/SM (occupancy fix)
// ---------------------------------------------------------------------------
__global__ __launch_bounds__(NTHR, 4) void fused_front_kernel(const float* __restrict__ img) {
    __shared__ __align__(16) unsigned char sbuf[SBUF_SZ];
    __shared__ float smax[NTHR / 32];

    uint64_t (*s_img)[40] = (uint64_t(*)[40])(sbuf + OFF_IMG);
    uint4    (*s_row)[36] = (uint4(*)[36])(sbuf + OFF_ROW);
    uint4    (*s_sm )[36] = (uint4(*)[36])(sbuf + OFF_SM);
    uint4    (*s_d  )[34] = (uint4(*)[34])(sbuf + OFF_D);
    uint4    (*s_s  )[34] = (uint4(*)[34])(sbuf + OFF_S);
    uint4    (*s_g2 )[34] = (uint4(*)[34])(sbuf + OFF_G2);
    uchar2   (*s_bin)[34] = (uchar2(*)[34])(sbuf + OFF_BIN);

    const int x0 = blockIdx.x * TX;
    const int y0 = blockIdx.y * TY;
    const int p  = blockIdx.z;
    const float* p0 = img + (size_t)(2 * p)     * IMG_HW;
    const float* p1 = img + (size_t)(2 * p + 1) * IMG_HW;
    const int tid = threadIdx.x;

    const float w5[5] = {0.054488684549640294f, 0.24420134200323337f,
                         0.4026199468935272f,  0.24420134200323337f,
                         0.054488684549640294f};
    uint64_t W[5];
#pragma unroll
    for (int k = 0; k < 5; k++) W[k] = pack2(w5[k], w5[k]);

    // ---- S1: load image tile (reflect once) ----
#pragma unroll 2
    for (int i = tid; i < 24 * 40; i += NTHR) {
        const int yy = i / 40, xx = i - yy * 40;
        const int gx = refl(x0 - 4 + xx, IMG_W);
        const int gy = refl(y0 - 4 + yy, IMG_H);
        const int gi = gy * IMG_W + gx;
        s_img[yy][xx] = pack2(p0[gi], p1[gi]);
    }
    __syncthreads();

    // ---- S2: row gaussian (x); all-positive -> Kahan ----
#pragma unroll 2
    for (int i = tid; i < 24 * 36; i += NTHR) {
        const int ry = i / 36, rx = i - ry * 36;
        uint64_t a0 = s_img[ry][rx];
        uint64_t ah = f2mul(W[0], a0);
        uint64_t al = f2fma(W[0], a0, f2neg(ah));
#pragma unroll
        for (int k = 1; k < 5; k++) {
            uint64_t ak = s_img[ry][rx + k];
            uint64_t pp = f2mul(W[k], ak);
            uint64_t ee = f2fma(W[k], ak, f2neg(pp));
            f2_kacc(ah, al, pp, ee);
        }
        s_row[ry][rx] = pk4(ah, al);
    }
    __syncthreads();

    // ---- S3: column gaussian (y); all-positive -> Kahan ----
#pragma unroll 2
    for (int i = tid; i < 20 * 36; i += NTHR) {
        const int sy = i / 36, sx = i - sy * 36;
        uint64_t h0, l0;
        upk4(s_row[sy][sx], h0, l0);
        uint64_t ah = f2mul(W[0], h0);
        uint64_t al = f2fma(W[0], h0, f2neg(ah));
        al = f2fma(W[0], l0, al);
#pragma unroll
        for (int k = 1; k < 5; k++) {
            uint64_t hk, lk;
            upk4(s_row[sy + k][sx], hk, lk);
            uint64_t pp = f2mul(W[k], hk);
            uint64_t ee = f2fma(W[k], hk, f2neg(pp));
            ee = f2fma(W[k], lk, ee);
            f2_kacc(ah, al, pp, ee);
        }
        s_sm[sy][sx] = pk4(ah, al);
    }
    __syncthreads();

    // ---- SC: per-row sobel intermediates  d = v2 - v0 (TwoSum),
    //          s = v0 + 2v1 + v2 (positive -> Kahan) ----
#pragma unroll 2
    for (int i = tid; i < 20 * 34; i += NTHR) {
        const int ry = i / 34, jx = i - ry * 34;
        uint64_t v0h, v0l, v1h, v1l, v2h, v2l;
        upk4(s_sm[ry][jx + 0], v0h, v0l);
        upk4(s_sm[ry][jx + 1], v1h, v1l);
        upk4(s_sm[ry][jx + 2], v2h, v2l);

        uint64_t dh = v2h, dl = v2l;
        f2_acc(dh, dl, f2neg(v0h), f2neg(v0l));

        uint64_t sh = v0h, sl = v0l;
        f2_kacc(sh, sl, f2add(v1h, v1h), f2add(v1l, v1l));
        f2_kacc(sh, sl, v2h, v2l);

        s_d[ry][jx] = pk4(dh, dl);
        s_s[ry][jx] = pk4(sh, sl);
    }
    __syncthreads();

    // ---- SD: gx = d0+2d1+d2, gy = s0-s2, g2 = gx^2+gy^2, bins (interior) ----
    const uint64_t T1H = pack2(0.41421357f,  0.41421357f);
    const uint64_t T1L = pack2(-7.3716195e-9f, -7.3716195e-9f);
    const uint64_t T2H = pack2(2.4142137f,   2.4142137f);
    const uint64_t T2L = pack2(-1.3773958e-7f, -1.3773958e-7f);

#pragma unroll 2
    for (int i = tid; i < 18 * 34; i += NTHR) {
        const int jy = i / 34, jx = i - jy * 34;
        uint64_t d0h, d0l, d1h, d1l, d2h, d2l, s0h, s0l, s2h, s2l;
        upk4(s_d[jy + 0][jx], d0h, d0l);
        upk4(s_d[jy + 1][jx], d1h, d1l);
        upk4(s_d[jy + 2][jx], d2h, d2l);
        upk4(s_s[jy + 0][jx], s0h, s0l);
        upk4(s_s[jy + 2][jx], s2h, s2l);

        uint64_t gxh = d0h, gxl = d0l;
        f2_acc(gxh, gxl, f2add(d1h, d1h), f2add(d1l, d1l));
        f2_acc(gxh, gxl, d2h, d2l);
        f2_renorm(gxh, gxl);

        uint64_t gyh = s0h, gyl = s0l;
        f2_acc(gyh, gyl, f2neg(s2h), f2neg(s2l));
        f2_renorm(gyh, gyl);

        uint64_t pa = f2mul(gxh, gxh);
        uint64_t ea = f2fma(gxh, gxh, f2neg(pa));
        ea = f2fma(f2add(gxh, gxh), gxl, ea);
        uint64_t pb = f2mul(gyh, gyh);
        uint64_t eb = f2fma(gyh, gyh, f2neg(pb));
        eb = f2fma(f2add(gyh, gyh), gyl, eb);
        uint64_t g2h = pa, g2l = ea;
        f2_acc(g2h, g2l, pb, eb);
        f2_renorm(g2h, g2l);
        s_g2[jy][jx] = pk4(g2h, g2l);

        if (jy >= 1 && jy <= TY && jx >= 1 && jx <= TX) {
            uint64_t sgx = gxh & 0x8000000080000000ull;
            uint64_t axh = gxh ^ sgx, axl = gxl ^ sgx;
            uint64_t sgy = gyh & 0x8000000080000000ull;
            uint64_t ayh = gyh ^ sgy, ayl = gyl ^ sgy;

            uint64_t m1h, m1l, m2h, m2l;
            df2_mul_const(T1H, T1L, axh, axl, m1h, m1l);
            df2_mul_const(T2H, T2L, axh, axl, m2h, m2l);

            uchar2 bb;
#pragma unroll
            for (int c = 0; c < 2; c++) {
                float AYH, AYL, M1Hf, M1Lf, M2Hf, M2Lf, GXH, GXL, GYH, GYL;
                if (c == 0) {
                    AYH = plo(ayh); AYL = plo(ayl);
                    M1Hf = plo(m1h); M1Lf = plo(m1l);
                    M2Hf = plo(m2h); M2Lf = plo(m2l);
                    GXH = plo(gxh); GXL = plo(gxl);
                    GYH = plo(gyh); GYL = plo(gyl);
                } else {
                    AYH = phi(ayh); AYL = phi(ayl);
                    M1Hf = phi(m1h); M1Lf = phi(m1l);
                    M2Hf = phi(m2h); M2Lf = phi(m2l);
                    GXH = phi(gxh); GXL = phi(gxl);
                    GYH = phi(gyh); GYL = phi(gyl);
                }
                unsigned char bin;
                if (AYH < M1Hf || (AYH == M1Hf && AYL < M1Lf)) bin = 0;
                else if (!(AYH < M2Hf || (AYH == M2Hf && AYL < M2Lf))) bin = 2;
                else {
                    const bool px = (GXH > 0.0f) || (GXH == 0.0f && GXL > 0.0f);
                    const bool py = (GYH > 0.0f) || (GYH == 0.0f && GYL > 0.0f);
                    bin = (px == py) ? 1 : 3;
                }
                if (c == 0) bb.x = bin; else bb.y = bin;
            }
            s_bin[jy][jx] = bb;
        }
    }
    __syncthreads();

    // ---- SE: NMS + sup + block max ----
    const int tx = tid & (TX - 1);
    const int ty = tid >> 5;

    uint64_t c_h, c_l;
    upk4(s_g2[ty + 1][tx + 1], c_h, c_l);
    const uchar2 bin2 = s_bin[ty + 1][tx + 1];

    float sup[2];
#pragma unroll
    for (int comp = 0; comp < 2; comp++) {
        const int bin = comp ? bin2.y : bin2.x;
        int ay, ax_, by, bx_;
        if (bin == 0)      { ay = ty + 1; ax_ = tx + 2; by = ty + 1; bx_ = tx + 0; }
        else if (bin == 2) { ay = ty + 0; ax_ = tx + 1; by = ty + 2; bx_ = tx + 1; }
        else if (bin == 1) { ay = ty + 2; ax_ = tx + 0; by = ty + 0; bx_ = tx + 2; }
        else               { ay = ty + 2; ax_ = tx + 2; by = ty + 0; bx_ = tx + 0; }

        uint64_t nAh, nAl, nBh, nBl;
        upk4(s_g2[ay][ax_], nAh, nAl);
        upk4(s_g2[by][bx_], nBh, nBl);

        float ch, cl, nah, nal, nbh, nbl;
        if (comp == 0) {
            ch = plo(c_h); cl = plo(c_l);
            nah = plo(nAh); nal = plo(nAl);
            nbh = plo(nBh); nbl = plo(nBl);
        } else {
            ch = phi(c_h); cl = phi(c_l);
            nah = phi(nAh); nal = phi(nAl);
            nbh = phi(nBh); nbl = phi(nBl);
        }

        float sv = 0.0f;
        if (dfp_gt(ch, cl, nah, nal) && dfp_gt(ch, cl, nbh, nbl))
            sv = sqrtf(ch);
        sup[comp] = sv;
    }

    g_sup2[(size_t)p * IMG_HW + (size_t)(y0 + ty) * IMG_W + (x0 + tx)] =
        make_float2(sup[0], sup[1]);

    float vmax = fmaxf(sup[0], sup[1]);
#pragma unroll
    for (int off = 16; off > 0; off >>= 1)
        vmax = fmaxf(vmax, __shfl_xor_sync(0xFFFFFFFF, vmax, off));
    const int wid = tid >> 5;
    if ((tid & 31) == 0) smax[wid] = vmax;
    __syncthreads();
    if (tid == 0) {
        float bmax = smax[0];
#pragma unroll
        for (int i = 1; i < NTHR / 32; i++) bmax = fmaxf(bmax, smax[i]);
        atomicMax(&g_max_bits, __float_as_uint(bmax));
    }
}

// ---------------------------------------------------------------------------
// Fused back: 4 batches (2 sup planes) per block; resets g_max at the end
// ---------------------------------------------------------------------------
__global__ __launch_bounds__(NTHR, 4) void fused_back_kernel(float* __restrict__ out) {
    __shared__ float2   s_sup[2][18][34];
    __shared__ uint64_t s_str[2][18][34];

    const int x0 = blockIdx.x * TX;
    const int y0 = blockIdx.y * TY;
    const int q  = blockIdx.z;               // quad index: batches 4q..4q+3
    const int tid = threadIdx.x;
    const float2* sup0 = g_sup2 + (size_t)(2 * q)     * IMG_HW;
    const float2* sup1 = g_sup2 + (size_t)(2 * q + 1) * IMG_HW;

    // min(sup) == 0 exactly (NMS always suppresses some pixels)
    const float mx   = __uint_as_float(g_max_bits);
    const float high = mx * 0.25f;
    const float low  = mx * 0.1f;

#pragma unroll 2
    for (int i = tid; i < 18 * 34; i += NTHR) {
        const int yy = i / 34, xx = i - yy * 34;
        const int gx = refl(x0 - 1 + xx, IMG_W);
        const int gy = refl(y0 - 1 + yy, IMG_H);
        const int gi = gy * IMG_W + gx;
        const float2 a = sup0[gi];
        const float2 b = sup1[gi];
        s_sup[0][yy][xx] = a;
        s_sup[1][yy][xx] = b;
        s_str[0][yy][xx] = pack2(sigm(100.0f * (a.x - high)),
                                 sigm(100.0f * (a.y - high)));
        s_str[1][yy][xx] = pack2(sigm(100.0f * (b.x - high)),
                                 sigm(100.0f * (b.y - high)));
    }
    __syncthreads();   // also guarantees every thread consumed g_max_bits

    const int tx = tid & (TX - 1);
    const int ty = tid >> 5;
    const size_t idx = (size_t)(y0 + ty) * IMG_W + (x0 + tx);

#pragma unroll
    for (int j = 0; j < 2; j++) {
        uint64_t hs = s_str[j][ty + 0][tx + 0];
        hs = f2add(hs, s_str[j][ty + 0][tx + 1]);
        hs = f2add(hs, s_str[j][ty + 0][tx + 2]);
        hs = f2add(hs, s_str[j][ty + 1][tx + 0]);
        hs = f2add(hs, s_str[j][ty + 1][tx + 1]);
        hs = f2add(hs, s_str[j][ty + 1][tx + 2]);
        hs = f2add(hs, s_str[j][ty + 2][tx + 0]);
        hs = f2add(hs, s_str[j][ty + 2][tx + 1]);
        hs = f2add(hs, s_str[j][ty + 2][tx + 2]);

        const uint64_t sc = s_str[j][ty + 1][tx + 1];
        const float2  sv  = s_sup[j][ty + 1][tx + 1];

        const float s0 = plo(sc), s1 = phi(sc);
        const float w0 = sigm(100.0f * (sv.x - low)) * (1.0f - s0);
        const float w1 = sigm(100.0f * (sv.y - low)) * (1.0f - s1);
        const float m0 = s0 + w0 * sigm(100.0f * (plo(hs) - 0.5f));
        const float m1 = s1 + w1 * sigm(100.0f * (phi(hs) - 0.5f));

        out[(size_t)(4 * q + 2 * j)     * IMG_HW + idx] = m0;
        out[(size_t)(4 * q + 2 * j + 1) * IMG_HW + idx] = m1;
    }

    // last-finishing block resets scalars for the next graph replay
    if (tid == 0) {
        const unsigned t = atomicAdd(&g_done, 1u);
        if (t == (unsigned)(NBLOCKS_BACK - 1)) {
            g_max_bits = 0u;
            g_done = 0u;
        }
    }
}

// ---------------------------------------------------------------------------
extern "C" void kernel_launch(void* const* d_in, const int* in_sizes, int n_in,
                              void* d_out, int out_size) {
    const float* image = (const float*)d_in[0];
    float* out = (float*)d_out;

    dim3 grdF(IMG_W / TX, IMG_H / TY, NPAIR);
    fused_front_kernel<<<grdF, NTHR>>>(image);

    dim3 grdB(IMG_W / TX, IMG_H / TY, 2);
    fused_back_kernel<<<grdB, NTHR>>>(out);
}

// round 13
// speedup vs baseline: 1.2207x; 1.0717x over previous
#include <cuda_runtime.h>
#include <math.h>
#include <stdint.h>

#define IMG_W 1024
#define IMG_H 1024
#define IMG_B 8
#define IMG_HW (IMG_H * IMG_W)

#define TX 32
#define TY 32          // front tile is now 32x32
#define NTHR 512
#define NPAIR 4
#define BTX 32
#define BTY 16         // back tile stays 32x16
#define NBLOCKS_BACK ((IMG_W / BTX) * (IMG_H / BTY) * 2)

// ---------------------------------------------------------------------------
// Scratch (allocation-free rule: __device__ globals; zero-initialized)
// ---------------------------------------------------------------------------
__device__ float2 g_sup2[(size_t)NPAIR * IMG_HW];
__device__ unsigned int g_max_bits;   // reset by last back block each launch
__device__ unsigned int g_done;

__device__ __forceinline__ int refl(int i, int n) {
    if (i < 0) i = -i;
    if (i >= n) i = 2 * n - 2 - i;
    return i;
}

// fast sigmoid: MUFU ex2 + approx reciprocal (smooth output path only)
__device__ __forceinline__ float sigm(float x) {
    float e = __expf(-x);
    float d = 1.0f + e;
    float r; asm("rcp.approx.f32 %0, %1;" : "=f"(r) : "f"(d));
    return r;
}

// ---------------------------------------------------------------------------
// Packed f32x2 primitives
// ---------------------------------------------------------------------------
__device__ __forceinline__ uint64_t f2add(uint64_t a, uint64_t b) {
    uint64_t r; asm("add.rn.f32x2 %0, %1, %2;" : "=l"(r) : "l"(a), "l"(b)); return r;
}
__device__ __forceinline__ uint64_t f2mul(uint64_t a, uint64_t b) {
    uint64_t r; asm("mul.rn.f32x2 %0, %1, %2;" : "=l"(r) : "l"(a), "l"(b)); return r;
}
__device__ __forceinline__ uint64_t f2fma(uint64_t a, uint64_t b, uint64_t c) {
    uint64_t r; asm("fma.rn.f32x2 %0, %1, %2, %3;" : "=l"(r) : "l"(a), "l"(b), "l"(c)); return r;
}
__device__ __forceinline__ uint64_t f2neg(uint64_t a) { return a ^ 0x8000000080000000ull; }

__device__ __forceinline__ uint64_t pack2(float lo, float hi) {
    return ((uint64_t)__float_as_uint(hi) << 32) | (uint64_t)__float_as_uint(lo);
}
__device__ __forceinline__ float plo(uint64_t v) { return __uint_as_float((unsigned)v); }
__device__ __forceinline__ float phi(uint64_t v) { return __uint_as_float((unsigned)(v >> 32)); }

#define NEG1_PK 0xBF800000BF800000ull

__device__ __forceinline__ uint64_t f2sub(uint64_t a, uint64_t b) {
    return f2fma(b, NEG1_PK, a);
}

// full TwoSum accumulate (sign-mixed sums): (ah, al) += (p, e)
__device__ __forceinline__ void f2_acc(uint64_t& ah, uint64_t& al,
                                       uint64_t p, uint64_t e) {
    uint64_t s  = f2add(ah, p);
    uint64_t bp = f2fma(ah, NEG1_PK, s);
    uint64_t ap = f2fma(bp, NEG1_PK, s);
    uint64_t eb = f2fma(bp, NEG1_PK, p);
    uint64_t ea = f2fma(ap, NEG1_PK, ah);
    ah = s;
    al = f2add(al, f2add(f2add(ea, eb), e));
}

// Kahan accumulate (all-positive sums): (ah, al) += (p, e)
__device__ __forceinline__ void f2_kacc(uint64_t& ah, uint64_t& al,
                                        uint64_t p, uint64_t e) {
    uint64_t s   = f2add(ah, p);
    uint64_t err = f2fma(s, NEG1_PK, ah);  // ah - s
    err = f2add(err, p);
    al  = f2add(al, f2add(err, e));
    ah  = s;
}

// Fast2Sum renorm
__device__ __forceinline__ void f2_renorm(uint64_t& h, uint64_t& l) {
    uint64_t hh = f2add(h, l);
    uint64_t t  = f2fma(h, NEG1_PK, hh);
    l = f2fma(t, NEG1_PK, l);
    h = hh;
}

// packed df-const × df, renormalized
__device__ __forceinline__ void df2_mul_const(uint64_t Th, uint64_t Tl,
                                              uint64_t ah, uint64_t al,
                                              uint64_t& mh, uint64_t& ml) {
    uint64_t p = f2mul(Th, ah);
    uint64_t e = f2fma(Th, ah, f2neg(p));
    e = f2fma(Th, al, e);
    e = f2fma(Tl, ah, e);
    mh = f2add(p, e);
    ml = f2sub(e, f2sub(mh, p));
}

__device__ __forceinline__ uint4 pk4(uint64_t h, uint64_t l) {
    uint4 r; r.x = (unsigned)h; r.y = (unsigned)(h >> 32);
    r.z = (unsigned)l; r.w = (unsigned)(l >> 32); return r;
}
__device__ __forceinline__ void upk4(uint4 v, uint64_t& h, uint64_t& l) {
    h = ((uint64_t)v.y << 32) | v.x;
    l = ((uint64_t)v.w << 32) | v.z;
}

__device__ __forceinline__ bool dfp_gt(float ah, float al, float bh, float bl) {
    return (ah > bh) || (ah == bh && al > bl);
}

// ---------------------------------------------------------------------------
// Dynamic shared-memory overlay (bytes), peak 59904:
//   sm  (36x36 uint4, 20736) @ 0      live S3-SC
//   row (40x36 uint4, 23040) @ 20736  live S2-S3
//   d   (36x34 uint4, 19584) @ 20736  live SC-SD  (over dead row head)
//   s   (36x34 uint4, 19584) @ 40320  live SC-SD  (over dead row tail/img)
//   img (40x40 u64,  12800)  @ 43776  live S1-S2  (under s, disjoint lifetime)
//   g2  (34x34 uint4, 18496) @ 0      live SD-SE  (over dead sm)
//   bin (34x34 uchar,  1156) @ 18496  live SD-SE  (gap before d @20736)
// ---------------------------------------------------------------------------
#define OFF_SM  0
#define OFF_ROW 20736
#define OFF_D   20736
#define OFF_S   40320
#define OFF_IMG 43776
#define OFF_G2  0
#define OFF_BIN 18496
#define SBUF_SZ 59904

// ---------------------------------------------------------------------------
// Fused front: img -> sep gauss -> sobel -> NMS -> sup (+max)
// 32x32 tile, dynamic smem, 3 blocks/SM
// ---------------------------------------------------------------------------
__global__ __launch_bounds__(NTHR, 3) void fused_front_kernel(const float* __restrict__ img) {
    extern __shared__ __align__(16) unsigned char sbuf[];
    __shared__ float smax[NTHR / 32];

    uint64_t (*s_img)[40] = (uint64_t(*)[40])(sbuf + OFF_IMG);
    uint4    (*s_row)[36] = (uint4(*)[36])(sbuf + OFF_ROW);
    uint4    (*s_sm )[36] = (uint4(*)[36])(sbuf + OFF_SM);
    uint4    (*s_d  )[34] = (uint4(*)[34])(sbuf + OFF_D);
    uint4    (*s_s  )[34] = (uint4(*)[34])(sbuf + OFF_S);
    uint4    (*s_g2 )[34] = (uint4(*)[34])(sbuf + OFF_G2);
    unsigned char (*s_bin)[34] = (unsigned char(*)[34])(sbuf + OFF_BIN);

    const int x0 = blockIdx.x * TX;
    const int y0 = blockIdx.y * TY;
    const int p  = blockIdx.z;
    const float* p0 = img + (size_t)(2 * p)     * IMG_HW;
    const float* p1 = img + (size_t)(2 * p + 1) * IMG_HW;
    const int tid = threadIdx.x;

    const float w5[5] = {0.054488684549640294f, 0.24420134200323337f,
                         0.4026199468935272f,  0.24420134200323337f,
                         0.054488684549640294f};
    uint64_t W[5];
#pragma unroll
    for (int k = 0; k < 5; k++) W[k] = pack2(w5[k], w5[k]);

    // ---- S1: load image tile 40x40 (reflect once) ----
#pragma unroll 2
    for (int i = tid; i < 40 * 40; i += NTHR) {
        const int yy = i / 40, xx = i - yy * 40;
        const int gx = refl(x0 - 4 + xx, IMG_W);
        const int gy = refl(y0 - 4 + yy, IMG_H);
        const int gi = gy * IMG_W + gx;
        s_img[yy][xx] = pack2(p0[gi], p1[gi]);
    }
    __syncthreads();

    // ---- S2: row gaussian (x), 40x36; all-positive -> Kahan ----
#pragma unroll 2
    for (int i = tid; i < 40 * 36; i += NTHR) {
        const int ry = i / 36, rx = i - ry * 36;
        uint64_t a0 = s_img[ry][rx];
        uint64_t ah = f2mul(W[0], a0);
        uint64_t al = f2fma(W[0], a0, f2neg(ah));
#pragma unroll
        for (int k = 1; k < 5; k++) {
            uint64_t ak = s_img[ry][rx + k];
            uint64_t pp = f2mul(W[k], ak);
            uint64_t ee = f2fma(W[k], ak, f2neg(pp));
            f2_kacc(ah, al, pp, ee);
        }
        s_row[ry][rx] = pk4(ah, al);
    }
    __syncthreads();

    // ---- S3: column gaussian (y), 36x36; all-positive -> Kahan ----
#pragma unroll 2
    for (int i = tid; i < 36 * 36; i += NTHR) {
        const int sy = i / 36, sx = i - sy * 36;
        uint64_t h0, l0;
        upk4(s_row[sy][sx], h0, l0);
        uint64_t ah = f2mul(W[0], h0);
        uint64_t al = f2fma(W[0], h0, f2neg(ah));
        al = f2fma(W[0], l0, al);
#pragma unroll
        for (int k = 1; k < 5; k++) {
            uint64_t hk, lk;
            upk4(s_row[sy + k][sx], hk, lk);
            uint64_t pp = f2mul(W[k], hk);
            uint64_t ee = f2fma(W[k], hk, f2neg(pp));
            ee = f2fma(W[k], lk, ee);
            f2_kacc(ah, al, pp, ee);
        }
        s_sm[sy][sx] = pk4(ah, al);
    }
    __syncthreads();

    // ---- SC: per-row sobel intermediates, 36x34:
    //          d = v2 - v0 (TwoSum), s = v0 + 2v1 + v2 (Kahan) ----
#pragma unroll 2
    for (int i = tid; i < 36 * 34; i += NTHR) {
        const int ry = i / 34, jx = i - ry * 34;
        uint64_t v0h, v0l, v1h, v1l, v2h, v2l;
        upk4(s_sm[ry][jx + 0], v0h, v0l);
        upk4(s_sm[ry][jx + 1], v1h, v1l);
        upk4(s_sm[ry][jx + 2], v2h, v2l);

        uint64_t dh = v2h, dl = v2l;
        f2_acc(dh, dl, f2neg(v0h), f2neg(v0l));

        uint64_t sh = v0h, sl = v0l;
        f2_kacc(sh, sl, f2add(v1h, v1h), f2add(v1l, v1l));
        f2_kacc(sh, sl, v2h, v2l);

        s_d[ry][jx] = pk4(dh, dl);
        s_s[ry][jx] = pk4(sh, sl);
    }
    __syncthreads();

    // ---- SD: gx = d0+2d1+d2, gy = s0-s2, g2 = gx^2+gy^2, bins (interior) ----
    const uint64_t T1H = pack2(0.41421357f,  0.41421357f);
    const uint64_t T1L = pack2(-7.3716195e-9f, -7.3716195e-9f);
    const uint64_t T2H = pack2(2.4142137f,   2.4142137f);
    const uint64_t T2L = pack2(-1.3773958e-7f, -1.3773958e-7f);

#pragma unroll 2
    for (int i = tid; i < 34 * 34; i += NTHR) {
        const int jy = i / 34, jx = i - jy * 34;
        uint64_t d0h, d0l, d1h, d1l, d2h, d2l, s0h, s0l, s2h, s2l;
        upk4(s_d[jy + 0][jx], d0h, d0l);
        upk4(s_d[jy + 1][jx], d1h, d1l);
        upk4(s_d[jy + 2][jx], d2h, d2l);
        upk4(s_s[jy + 0][jx], s0h, s0l);
        upk4(s_s[jy + 2][jx], s2h, s2l);

        uint64_t gxh = d0h, gxl = d0l;
        f2_acc(gxh, gxl, f2add(d1h, d1h), f2add(d1l, d1l));
        f2_acc(gxh, gxl, d2h, d2l);
        f2_renorm(gxh, gxl);

        uint64_t gyh = s0h, gyl = s0l;
        f2_acc(gyh, gyl, f2neg(s2h), f2neg(s2l));
        f2_renorm(gyh, gyl);

        uint64_t pa = f2mul(gxh, gxh);
        uint64_t ea = f2fma(gxh, gxh, f2neg(pa));
        ea = f2fma(f2add(gxh, gxh), gxl, ea);
        uint64_t pb = f2mul(gyh, gyh);
        uint64_t eb = f2fma(gyh, gyh, f2neg(pb));
        eb = f2fma(f2add(gyh, gyh), gyl, eb);
        uint64_t g2h = pa, g2l = ea;
        f2_acc(g2h, g2l, pb, eb);
        f2_renorm(g2h, g2l);
        s_g2[jy][jx] = pk4(g2h, g2l);

        if (jy >= 1 && jy <= TY && jx >= 1 && jx <= TX) {
            uint64_t sgx = gxh & 0x8000000080000000ull;
            uint64_t axh = gxh ^ sgx, axl = gxl ^ sgx;
            uint64_t sgy = gyh & 0x8000000080000000ull;
            uint64_t ayh = gyh ^ sgy, ayl = gyl ^ sgy;

            uint64_t m1h, m1l, m2h, m2l;
            df2_mul_const(T1H, T1L, axh, axl, m1h, m1l);
            df2_mul_const(T2H, T2L, axh, axl, m2h, m2l);

            unsigned char packed_bins = 0;
#pragma unroll
            for (int c = 0; c < 2; c++) {
                float AYH, AYL, M1Hf, M1Lf, M2Hf, M2Lf, GXH, GXL, GYH, GYL;
                if (c == 0) {
                    AYH = plo(ayh); AYL = plo(ayl);
                    M1Hf = plo(m1h); M1Lf = plo(m1l);
                    M2Hf = plo(m2h); M2Lf = plo(m2l);
                    GXH = plo(gxh); GXL = plo(gxl);
                    GYH = plo(gyh); GYL = plo(gyl);
                } else {
                    AYH = phi(ayh); AYL = phi(ayl);
                    M1Hf = phi(m1h); M1Lf = phi(m1l);
                    M2Hf = phi(m2h); M2Lf = phi(m2l);
                    GXH = phi(gxh); GXL = phi(gxl);
                    GYH = phi(gyh); GYL = phi(gyl);
                }
                unsigned char bin;
                if (AYH < M1Hf || (AYH == M1Hf && AYL < M1Lf)) bin = 0;       // E/W
                else if (!(AYH < M2Hf || (AYH == M2Hf && AYL < M2Lf))) bin = 2; // N/S
                else {
                    const bool px = (GXH > 0.0f) || (GXH == 0.0f && GXL > 0.0f);
                    const bool py = (GYH > 0.0f) || (GYH == 0.0f && GYL > 0.0f);
                    bin = (px == py) ? 1 : 3;                                  // SW/NE : SE/NW
                }
                packed_bins |= bin << (2 * c);
            }
            s_bin[jy][jx] = packed_bins;
        }
    }
    __syncthreads();

    // ---- SE: NMS + sup + block max (2 output rows per thread) ----
    const int tx = tid & (TX - 1);
    const int ty = tid >> 5;   // 0..15

    float vmax = 0.0f;
#pragma unroll
    for (int half = 0; half < 2; half++) {
        const int oy = ty + half * 16;

        uint64_t c_h, c_l;
        upk4(s_g2[oy + 1][tx + 1], c_h, c_l);
        const unsigned char pb2 = s_bin[oy + 1][tx + 1];

        float sup[2];
#pragma unroll
        for (int comp = 0; comp < 2; comp++) {
            const int bin = (pb2 >> (2 * comp)) & 3;
            int ay, ax_, by, bx_;
            if (bin == 0)      { ay = oy + 1; ax_ = tx + 2; by = oy + 1; bx_ = tx + 0; } // E,W
            else if (bin == 2) { ay = oy + 0; ax_ = tx + 1; by = oy + 2; bx_ = tx + 1; } // N,S
            else if (bin == 1) { ay = oy + 2; ax_ = tx + 0; by = oy + 0; bx_ = tx + 2; } // SW,NE
            else               { ay = oy + 2; ax_ = tx + 2; by = oy + 0; bx_ = tx + 0; } // SE,NW

            uint64_t nAh, nAl, nBh, nBl;
            upk4(s_g2[ay][ax_], nAh, nAl);
            upk4(s_g2[by][bx_], nBh, nBl);

            float ch, cl, nah, nal, nbh, nbl;
            if (comp == 0) {
                ch = plo(c_h); cl = plo(c_l);
                nah = plo(nAh); nal = plo(nAl);
                nbh = plo(nBh); nbl = plo(nBl);
            } else {
                ch = phi(c_h); cl = phi(c_l);
                nah = phi(nAh); nal = phi(nAl);
                nbh = phi(nBh); nbl = phi(nBl);
            }

            float sv = 0.0f;
            if (dfp_gt(ch, cl, nah, nal) && dfp_gt(ch, cl, nbh, nbl))
                sv = sqrtf(ch);
            sup[comp] = sv;
        }

        g_sup2[(size_t)p * IMG_HW + (size_t)(y0 + oy) * IMG_W + (x0 + tx)] =
            make_float2(sup[0], sup[1]);
        vmax = fmaxf(vmax, fmaxf(sup[0], sup[1]));
    }

    // block max (sup >= 0 -> uint order == float order); min is provably 0
#pragma unroll
    for (int off = 16; off > 0; off >>= 1)
        vmax = fmaxf(vmax, __shfl_xor_sync(0xFFFFFFFF, vmax, off));
    const int wid = tid >> 5;
    if ((tid & 31) == 0) smax[wid] = vmax;
    __syncthreads();
    if (tid == 0) {
        float bmax = smax[0];
#pragma unroll
        for (int i = 1; i < NTHR / 32; i++) bmax = fmaxf(bmax, smax[i]);
        atomicMax(&g_max_bits, __float_as_uint(bmax));
    }
}

// ---------------------------------------------------------------------------
// Fused back: 4 batches (2 sup planes) per block; resets g_max at the end
// ---------------------------------------------------------------------------
__global__ __launch_bounds__(NTHR, 4) void fused_back_kernel(float* __restrict__ out) {
    __shared__ float2   s_sup[2][18][34];
    __shared__ uint64_t s_str[2][18][34];

    const int x0 = blockIdx.x * BTX;
    const int y0 = blockIdx.y * BTY;
    const int q  = blockIdx.z;               // quad index: batches 4q..4q+3
    const int tid = threadIdx.x;
    const float2* sup0 = g_sup2 + (size_t)(2 * q)     * IMG_HW;
    const float2* sup1 = g_sup2 + (size_t)(2 * q + 1) * IMG_HW;

    // min(sup) == 0 exactly (NMS always suppresses some pixels)
    const float mx   = __uint_as_float(g_max_bits);
    const float high = mx * 0.25f;
    const float low  = mx * 0.1f;

#pragma unroll 2
    for (int i = tid; i < 18 * 34; i += NTHR) {
        const int yy = i / 34, xx = i - yy * 34;
        const int gx = refl(x0 - 1 + xx, IMG_W);
        const int gy = refl(y0 - 1 + yy, IMG_H);
        const int gi = gy * IMG_W + gx;
        const float2 a = sup0[gi];
        const float2 b = sup1[gi];
        s_sup[0][yy][xx] = a;
        s_sup[1][yy][xx] = b;
        s_str[0][yy][xx] = pack2(sigm(100.0f * (a.x - high)),
                                 sigm(100.0f * (a.y - high)));
        s_str[1][yy][xx] = pack2(sigm(100.0f * (b.x - high)),
                                 sigm(100.0f * (b.y - high)));
    }
    __syncthreads();   // also guarantees every thread consumed g_max_bits

    const int tx = tid & (BTX - 1);
    const int ty = tid >> 5;
    const size_t idx = (size_t)(y0 + ty) * IMG_W + (x0 + tx);

#pragma unroll
    for (int j = 0; j < 2; j++) {
        uint64_t hs = s_str[j][ty + 0][tx + 0];
        hs = f2add(hs, s_str[j][ty + 0][tx + 1]);
        hs = f2add(hs, s_str[j][ty + 0][tx + 2]);
        hs = f2add(hs, s_str[j][ty + 1][tx + 0]);
        hs = f2add(hs, s_str[j][ty + 1][tx + 1]);
        hs = f2add(hs, s_str[j][ty + 1][tx + 2]);
        hs = f2add(hs, s_str[j][ty + 2][tx + 0]);
        hs = f2add(hs, s_str[j][ty + 2][tx + 1]);
        hs = f2add(hs, s_str[j][ty + 2][tx + 2]);

        const uint64_t sc = s_str[j][ty + 1][tx + 1];
        const float2  sv  = s_sup[j][ty + 1][tx + 1];

        const float s0 = plo(sc), s1 = phi(sc);
        const float w0 = sigm(100.0f * (sv.x - low)) * (1.0f - s0);
        const float w1 = sigm(100.0f * (sv.y - low)) * (1.0f - s1);
        const float m0 = s0 + w0 * sigm(100.0f * (plo(hs) - 0.5f));
        const float m1 = s1 + w1 * sigm(100.0f * (phi(hs) - 0.5f));

        out[(size_t)(4 * q + 2 * j)     * IMG_HW + idx] = m0;
        out[(size_t)(4 * q + 2 * j + 1) * IMG_HW + idx] = m1;
    }

    // last-finishing block resets scalars for the next graph replay
    if (tid == 0) {
        const unsigned t = atomicAdd(&g_done, 1u);
        if (t == (unsigned)(NBLOCKS_BACK - 1)) {
            g_max_bits = 0u;
            g_done = 0u;
        }
    }
}

// ---------------------------------------------------------------------------
extern "C" void kernel_launch(void* const* d_in, const int* in_sizes, int n_in,
                              void* d_out, int out_size) {
    const float* image = (const float*)d_in[0];
    float* out = (float*)d_out;

    // Host-side attribute set (not a stream op; legal during graph capture;
    // deterministic and idempotent on every call).
    cudaFuncSetAttribute(fused_front_kernel,
                         cudaFuncAttributeMaxDynamicSharedMemorySize, SBUF_SZ);

    dim3 grdF(IMG_W / TX, IMG_H / TY, NPAIR);
    fused_front_kernel<<<grdF, NTHR, SBUF_SZ>>>(image);

    dim3 grdB(IMG_W / BTX, IMG_H / BTY, 2);
    fused_back_kernel<<<grdB, NTHR>>>(out);
}

// round 14
// speedup vs baseline: 1.8522x; 1.5174x over previous
#include <cuda_runtime.h>
#include <math.h>
#include <stdint.h>

#define IMG_W 1024
#define IMG_H 1024
#define IMG_B 8
#define IMG_HW (IMG_H * IMG_W)

#define TX 32
#define TY 32
#define NTHR 512
#define NPAIR 4
#define BTX 32
#define BTY 16
#define NBLOCKS_BACK ((IMG_W / BTX) * (IMG_H / BTY) * 2)

// ---------------------------------------------------------------------------
// Scratch (allocation-free rule: __device__ globals; zero-initialized)
// ---------------------------------------------------------------------------
__device__ float2 g_sup2[(size_t)NPAIR * IMG_HW];
__device__ unsigned int g_max_bits;   // reset by last back block each launch
__device__ unsigned int g_done;

__device__ __forceinline__ int refl(int i, int n) {
    if (i < 0) i = -i;
    if (i >= n) i = 2 * n - 2 - i;
    return i;
}

// fast sigmoid (smooth output path only)
__device__ __forceinline__ float sigm(float x) {
    float e = __expf(-x);
    float d = 1.0f + e;
    float r; asm("rcp.approx.f32 %0, %1;" : "=f"(r) : "f"(d));
    return r;
}

// packed helpers for the back kernel
__device__ __forceinline__ uint64_t f2add(uint64_t a, uint64_t b) {
    uint64_t r; asm("add.rn.f32x2 %0, %1, %2;" : "=l"(r) : "l"(a), "l"(b)); return r;
}
__device__ __forceinline__ uint64_t pack2(float lo, float hi) {
    return ((uint64_t)__float_as_uint(hi) << 32) | (uint64_t)__float_as_uint(lo);
}
__device__ __forceinline__ float plo(uint64_t v) { return __uint_as_float((unsigned)v); }
__device__ __forceinline__ float phi(uint64_t v) { return __uint_as_float((unsigned)(v >> 32)); }

// ---------------------------------------------------------------------------
// Exact fp32 -> Q0.27 u32 (round-to-nearest; mantissa shift, no fp rounding)
// ---------------------------------------------------------------------------
__device__ __forceinline__ unsigned q27(float v) {
    const unsigned bits = __float_as_uint(v);       // v >= 0
    const int e = (int)(bits >> 23);                // biased exponent
    const unsigned m = (bits & 0x7fffffu) | 0x800000u;
    const int sh = e - 123;                         // v*2^27 = m * 2^sh
    if (sh >= 0) return m << sh;                    // v < 1 -> sh <= 3
    const int k = -sh;
    return (k < 32) ? ((m + (1u << (k - 1))) >> k) : 0u;
}

// Exact fp32 weight -> Q0.32 u32 (weights have ulp >= 2^-29: exact)
__device__ __forceinline__ unsigned wq32(float w) {
    const unsigned bits = __float_as_uint(w);
    const unsigned m = (bits & 0x7fffffu) | 0x800000u;
    const int sh = (int)(bits >> 23) - 118;         // w*2^32 = m << sh
    return m << sh;
}

// round(tan(22.5 deg) * 2^32)
#define T1U 1779033704u

// ---------------------------------------------------------------------------
// Shared overlay (bytes), peak 34688 (static):
//   img (40x40 u64, 12800) @ 0      live S1-S2
//   row (40x36 u64, 11520) @ 12800  live S2-S3
//   sm  (36x36 u64, 10368) @ 24320  live S3-SD
//   g2  (34x34 u128,18496) @ 0      live SD-SE (over dead img/row)
//   bin (34x34 u8,   1156) @ 18496  live SD-SE
// ---------------------------------------------------------------------------
#define OFF_IMG 0
#define OFF_ROW 12800
#define OFF_SM  24320
#define OFF_G2  0
#define OFF_BIN 18496
#define SBUF_SZ 34688

// ---------------------------------------------------------------------------
// Fused front (integer pipeline): img -> gauss -> sobel -> NMS -> sup (+max)
// ---------------------------------------------------------------------------
__global__ __launch_bounds__(NTHR, 4) void fused_front_kernel(const float* __restrict__ img) {
    __shared__ __align__(16) unsigned char sbuf[SBUF_SZ];
    __shared__ float smax[NTHR / 32];

    uint64_t (*s_img)[40] = (uint64_t(*)[40])(sbuf + OFF_IMG);
    uint64_t (*s_row)[36] = (uint64_t(*)[36])(sbuf + OFF_ROW);
    uint64_t (*s_sm )[36] = (uint64_t(*)[36])(sbuf + OFF_SM);
    uint4    (*s_g2 )[34] = (uint4(*)[34])(sbuf + OFF_G2);
    unsigned char (*s_bin)[34] = (unsigned char(*)[34])(sbuf + OFF_BIN);

    const int x0 = blockIdx.x * TX;
    const int y0 = blockIdx.y * TY;
    const int p  = blockIdx.z;
    const float* p0 = img + (size_t)(2 * p)     * IMG_HW;
    const float* p1 = img + (size_t)(2 * p + 1) * IMG_HW;
    const int tid = threadIdx.x;

    const float w5[5] = {0.054488684549640294f, 0.24420134200323337f,
                         0.4026199468935272f,  0.24420134200323337f,
                         0.054488684549640294f};
    unsigned W[5];
#pragma unroll
    for (int k = 0; k < 5; k++) W[k] = wq32(w5[k]);

    // ---- S1: load + quantize image tile 40x40 (reflect once) ----
#pragma unroll 2
    for (int i = tid; i < 40 * 40; i += NTHR) {
        const int yy = i / 40, xx = i - yy * 40;
        const int gx = refl(x0 - 4 + xx, IMG_W);
        const int gy = refl(y0 - 4 + yy, IMG_H);
        const int gi = gy * IMG_W + gx;
        const unsigned a = q27(p0[gi]);
        const unsigned b = q27(p1[gi]);
        s_img[yy][xx] = ((uint64_t)b << 32) | a;
    }
    __syncthreads();

    // ---- S2: row gaussian (x): exact u32xu32->u64 MACs, round to Q0.29 ----
#pragma unroll 2
    for (int i = tid; i < 40 * 36; i += NTHR) {
        const int ry = i / 36, rx = i - ry * 36;
        uint64_t acc0 = 0, acc1 = 0;
#pragma unroll
        for (int k = 0; k < 5; k++) {
            const uint64_t v = s_img[ry][rx + k];
            acc0 += (uint64_t)W[k] * (unsigned)v;
            acc1 += (uint64_t)W[k] * (unsigned)(v >> 32);
        }
        const unsigned r0 = (unsigned)((acc0 + (1u << 29)) >> 30);
        const unsigned r1 = (unsigned)((acc1 + (1u << 29)) >> 30);
        s_row[ry][rx] = ((uint64_t)r1 << 32) | r0;
    }
    __syncthreads();

    // ---- S3: column gaussian (y): exact MACs, round to Q0.29 ----
#pragma unroll 2
    for (int i = tid; i < 36 * 36; i += NTHR) {
        const int sy = i / 36, sx = i - sy * 36;
        uint64_t acc0 = 0, acc1 = 0;
#pragma unroll
        for (int k = 0; k < 5; k++) {
            const uint64_t v = s_row[sy + k][sx];
            acc0 += (uint64_t)W[k] * (unsigned)v;
            acc1 += (uint64_t)W[k] * (unsigned)(v >> 32);
        }
        const unsigned r0 = (unsigned)((acc0 + (1u << 31)) >> 32);
        const unsigned r1 = (unsigned)((acc1 + (1u << 31)) >> 32);
        s_sm[sy][sx] = ((uint64_t)r1 << 32) | r0;
    }
    __syncthreads();

    // ---- SD: sobel + g2 + bins (exact int32/int64) ----
#pragma unroll 2
    for (int i = tid; i < 34 * 34; i += NTHR) {
        const int jy = i / 34, jx = i - jy * 34;
        const uint64_t a0 = s_sm[jy + 0][jx + 0];
        const uint64_t a1 = s_sm[jy + 0][jx + 1];
        const uint64_t a2 = s_sm[jy + 0][jx + 2];
        const uint64_t b0 = s_sm[jy + 1][jx + 0];
        const uint64_t b2 = s_sm[jy + 1][jx + 2];
        const uint64_t c0 = s_sm[jy + 2][jx + 0];
        const uint64_t c1 = s_sm[jy + 2][jx + 1];
        const uint64_t c2 = s_sm[jy + 2][jx + 2];

        const bool interior = (jy >= 1 && jy <= TY && jx >= 1 && jx <= TX);

        uint64_t g2v[2];
        unsigned char packed_bins = 0;
#pragma unroll
        for (int c = 0; c < 2; c++) {
            const int sh = c * 32;
            const int v00 = (int)(unsigned)(a0 >> sh), v01 = (int)(unsigned)(a1 >> sh),
                      v02 = (int)(unsigned)(a2 >> sh);
            const int v10 = (int)(unsigned)(b0 >> sh), v12 = (int)(unsigned)(b2 >> sh);
            const int v20 = (int)(unsigned)(c0 >> sh), v21 = (int)(unsigned)(c1 >> sh),
                      v22 = (int)(unsigned)(c2 >> sh);

            const int d0 = v02 - v00, d1 = v12 - v10, d2 = v22 - v20;
            const int gx = d0 + 2 * d1 + d2;
            const int s0 = v00 + 2 * v01 + v02;
            const int s2 = v20 + 2 * v21 + v22;
            const int gy = s0 - s2;

            g2v[c] = (uint64_t)((long long)gx * gx + (long long)gy * gy);

            if (interior) {
                const unsigned ax = (unsigned)(gx < 0 ? -gx : gx);
                const unsigned ay = (unsigned)(gy < 0 ? -gy : gy);
                unsigned char bin;
                if (((uint64_t)ay << 32) < (uint64_t)T1U * ax)       bin = 0; // E/W
                else if (((uint64_t)ax << 32) <= (uint64_t)T1U * ay) bin = 2; // N/S
                else bin = ((gx > 0) == (gy > 0)) ? 1 : 3;                    // SW/NE : SE/NW
                packed_bins |= bin << (2 * c);
            }
        }
        uint4 st;
        st.x = (unsigned)g2v[0]; st.y = (unsigned)(g2v[0] >> 32);
        st.z = (unsigned)g2v[1]; st.w = (unsigned)(g2v[1] >> 32);
        s_g2[jy][jx] = st;
        if (interior) s_bin[jy][jx] = packed_bins;
    }
    __syncthreads();

    // ---- SE: NMS (exact int64 compares) + sup + block max ----
    const int tx = tid & (TX - 1);
    const int ty = tid >> 5;   // 0..15

    float vmax = 0.0f;
#pragma unroll
    for (int half = 0; half < 2; half++) {
        const int oy = ty + half * 16;

        const uint4 cv = s_g2[oy + 1][tx + 1];
        const unsigned char pb2 = s_bin[oy + 1][tx + 1];

        float sup[2];
#pragma unroll
        for (int comp = 0; comp < 2; comp++) {
            const int bin = (pb2 >> (2 * comp)) & 3;
            int ay, ax_, by, bx_;
            if (bin == 0)      { ay = oy + 1; ax_ = tx + 2; by = oy + 1; bx_ = tx + 0; } // E,W
            else if (bin == 2) { ay = oy + 0; ax_ = tx + 1; by = oy + 2; bx_ = tx + 1; } // N,S
            else if (bin == 1) { ay = oy + 2; ax_ = tx + 0; by = oy + 0; bx_ = tx + 2; } // SW,NE
            else               { ay = oy + 2; ax_ = tx + 2; by = oy + 0; bx_ = tx + 0; } // SE,NW

            const uint4 nA = s_g2[ay][ax_];
            const uint4 nB = s_g2[by][bx_];

            uint64_t cc, va, vb;
            if (comp == 0) {
                cc = ((uint64_t)cv.y << 32) | cv.x;
                va = ((uint64_t)nA.y << 32) | nA.x;
                vb = ((uint64_t)nB.y << 32) | nB.x;
            } else {
                cc = ((uint64_t)cv.w << 32) | cv.z;
                va = ((uint64_t)nA.w << 32) | nA.x * 0u + nA.z;  // (use z/w pair)
                va = ((uint64_t)nA.w << 32) | nA.z;
                vb = ((uint64_t)nB.w << 32) | nB.z;
            }

            float sv = 0.0f;
            if (cc > va && cc > vb)
                sv = sqrtf((float)cc) * 0x1p-29f;   // g2 is Q0.58 -> sqrt scale 2^-29
            sup[comp] = sv;
        }

        g_sup2[(size_t)p * IMG_HW + (size_t)(y0 + oy) * IMG_W + (x0 + tx)] =
            make_float2(sup[0], sup[1]);
        vmax = fmaxf(vmax, fmaxf(sup[0], sup[1]));
    }

    // block max (sup >= 0 -> uint order == float order); min is provably 0
#pragma unroll
    for (int off = 16; off > 0; off >>= 1)
        vmax = fmaxf(vmax, __shfl_xor_sync(0xFFFFFFFF, vmax, off));
    const int wid = tid >> 5;
    if ((tid & 31) == 0) smax[wid] = vmax;
    __syncthreads();
    if (tid == 0) {
        float bmax = smax[0];
#pragma unroll
        for (int i = 1; i < NTHR / 32; i++) bmax = fmaxf(bmax, smax[i]);
        atomicMax(&g_max_bits, __float_as_uint(bmax));
    }
}

// ---------------------------------------------------------------------------
// Fused back: 4 batches (2 sup planes) per block; resets g_max at the end
// ---------------------------------------------------------------------------
__global__ __launch_bounds__(NTHR, 4) void fused_back_kernel(float* __restrict__ out) {
    __shared__ float2   s_sup[2][18][34];
    __shared__ uint64_t s_str[2][18][34];

    const int x0 = blockIdx.x * BTX;
    const int y0 = blockIdx.y * BTY;
    const int q  = blockIdx.z;
    const int tid = threadIdx.x;
    const float2* sup0 = g_sup2 + (size_t)(2 * q)     * IMG_HW;
    const float2* sup1 = g_sup2 + (size_t)(2 * q + 1) * IMG_HW;

    // min(sup) == 0 exactly (NMS always suppresses some pixels)
    const float mx   = __uint_as_float(g_max_bits);
    const float high = mx * 0.25f;
    const float low  = mx * 0.1f;

#pragma unroll 2
    for (int i = tid; i < 18 * 34; i += NTHR) {
        const int yy = i / 34, xx = i - yy * 34;
        const int gx = refl(x0 - 1 + xx, IMG_W);
        const int gy = refl(y0 - 1 + yy, IMG_H);
        const int gi = gy * IMG_W + gx;
        const float2 a = sup0[gi];
        const float2 b = sup1[gi];
        s_sup[0][yy][xx] = a;
        s_sup[1][yy][xx] = b;
        s_str[0][yy][xx] = pack2(sigm(100.0f * (a.x - high)),
                                 sigm(100.0f * (a.y - high)));
        s_str[1][yy][xx] = pack2(sigm(100.0f * (b.x - high)),
                                 sigm(100.0f * (b.y - high)));
    }
    __syncthreads();   // also guarantees every thread consumed g_max_bits

    const int tx = tid & (BTX - 1);
    const int ty = tid >> 5;
    const size_t idx = (size_t)(y0 + ty) * IMG_W + (x0 + tx);

#pragma unroll
    for (int j = 0; j < 2; j++) {
        uint64_t hs = s_str[j][ty + 0][tx + 0];
        hs = f2add(hs, s_str[j][ty + 0][tx + 1]);
        hs = f2add(hs, s_str[j][ty + 0][tx + 2]);
        hs = f2add(hs, s_str[j][ty + 1][tx + 0]);
        hs = f2add(hs, s_str[j][ty + 1][tx + 1]);
        hs = f2add(hs, s_str[j][ty + 1][tx + 2]);
        hs = f2add(hs, s_str[j][ty + 2][tx + 0]);
        hs = f2add(hs, s_str[j][ty + 2][tx + 1]);
        hs = f2add(hs, s_str[j][ty + 2][tx + 2]);

        const uint64_t sc = s_str[j][ty + 1][tx + 1];
        const float2  sv  = s_sup[j][ty + 1][tx + 1];

        const float s0 = plo(sc), s1 = phi(sc);
        const float w0 = sigm(100.0f * (sv.x - low)) * (1.0f - s0);
        const float w1 = sigm(100.0f * (sv.y - low)) * (1.0f - s1);
        const float m0 = s0 + w0 * sigm(100.0f * (plo(hs) - 0.5f));
        const float m1 = s1 + w1 * sigm(100.0f * (phi(hs) - 0.5f));

        out[(size_t)(4 * q + 2 * j)     * IMG_HW + idx] = m0;
        out[(size_t)(4 * q + 2 * j + 1) * IMG_HW + idx] = m1;
    }

    // last-finishing block resets scalars for the next graph replay
    if (tid == 0) {
        const unsigned t = atomicAdd(&g_done, 1u);
        if (t == (unsigned)(NBLOCKS_BACK - 1)) {
            g_max_bits = 0u;
            g_done = 0u;
        }
    }
}

// ---------------------------------------------------------------------------
extern "C" void kernel_launch(void* const* d_in, const int* in_sizes, int n_in,
                              void* d_out, int out_size) {
    const float* image = (const float*)d_in[0];
    float* out = (float*)d_out;

    dim3 grdF(IMG_W / TX, IMG_H / TY, NPAIR);
    fused_front_kernel<<<grdF, NTHR>>>(image);

    dim3 grdB(IMG_W / BTX, IMG_H / BTY, 2);
    fused_back_kernel<<<grdB, NTHR>>>(out);
}